// round 4
// baseline (speedup 1.0000x reference)
#include <cuda_runtime.h>
#include <cstdint>

#define NNODES 50000
#define MAXE   800000
#define IN_DIM 256
#define HID    128
#define OUTD   16
#define EPSB   1e-5f

// ---------------- scratch (static device globals; no allocation) ----------------
__device__ float g_deg [NNODES];
__device__ float g_dinv[NNODES];
__device__ float g_bufA[(size_t)NNODES * HID]; // t  (dinv-scaled h@W)
__device__ float g_bufB[(size_t)NNODES * HID]; // agg (scatter target); also agg3 (first N*16)
__device__ float g_bufC[(size_t)NNODES * HID]; // h  (post BN+ReLU)
__device__ float g_sum [HID];
__device__ float g_sq  [HID];
__device__ float g_mean[HID];
__device__ float g_istd[HID];

// ---------------- degree / dinv ----------------
__global__ void k_init_deg(float* deg, int n) {
    int i = blockIdx.x * blockDim.x + threadIdx.x;
    if (i < n) deg[i] = 1.0f;  // self-loop
}

__global__ void k_count_deg(const int* __restrict__ ei, float* deg, int E) {
    int i = blockIdx.x * blockDim.x + threadIdx.x;
    if (i < E) {
        int d = ei[E + i];  // dst row
        atomicAdd(&deg[d], 1.0f);
    }
}

__global__ void k_dinv(const float* __restrict__ deg, float* dinv, int n) {
    int i = blockIdx.x * blockDim.x + threadIdx.x;
    if (i < n) dinv[i] = rsqrtf(deg[i]);  // deg >= 1 always
}

// ---------------- SGEMM: T = dinv .* (A @ W), AGG = T  (Ncols = 128) ----------------
// BM=128, BN=128, BK=16, 256 threads, 8x8 micro-tile.
__global__ __launch_bounds__(256) void k_gemm128(
    const float* __restrict__ A, const float* __restrict__ W,
    const float* __restrict__ dinv, float* __restrict__ T, float* __restrict__ AGG,
    int nrows, int K)
{
    __shared__ float As[16][128];
    __shared__ float Bs[16][128];
    int tid = threadIdx.x;
    int tr = tid >> 4;        // 0..15  (row group)
    int tc = tid & 15;        // 0..15  (col group)
    int rowBase = blockIdx.x * 128;

    float acc[8][8];
    #pragma unroll
    for (int i = 0; i < 8; i++)
        #pragma unroll
        for (int j = 0; j < 8; j++) acc[i][j] = 0.f;

    for (int k0 = 0; k0 < K; k0 += 16) {
        // A tile: 128 rows x 16 k, stored transposed As[k][m]
        #pragma unroll
        for (int v = tid; v < 512; v += 256) {
            int r  = v >> 2;
            int c4 = (v & 3) << 2;
            int row = rowBase + r;
            float4 val = make_float4(0.f, 0.f, 0.f, 0.f);
            if (row < nrows) val = *(const float4*)&A[(size_t)row * K + k0 + c4];
            As[c4 + 0][r] = val.x; As[c4 + 1][r] = val.y;
            As[c4 + 2][r] = val.z; As[c4 + 3][r] = val.w;
        }
        // W tile: 16 k x 128 n, row-major
        #pragma unroll
        for (int v = tid; v < 512; v += 256) {
            int kk = v >> 5;
            int c4 = (v & 31) << 2;
            *(float4*)&Bs[kk][c4] = *(const float4*)&W[(size_t)(k0 + kk) * 128 + c4];
        }
        __syncthreads();

        #pragma unroll
        for (int kk = 0; kk < 16; kk++) {
            float4 m0 = *(float4*)&As[kk][tr * 8];
            float4 m1 = *(float4*)&As[kk][tr * 8 + 4];
            float4 n0 = *(float4*)&Bs[kk][tc * 8];
            float4 n1 = *(float4*)&Bs[kk][tc * 8 + 4];
            float rm[8] = {m0.x, m0.y, m0.z, m0.w, m1.x, m1.y, m1.z, m1.w};
            float rn[8] = {n0.x, n0.y, n0.z, n0.w, n1.x, n1.y, n1.z, n1.w};
            #pragma unroll
            for (int i = 0; i < 8; i++)
                #pragma unroll
                for (int j = 0; j < 8; j++)
                    acc[i][j] += rm[i] * rn[j];
        }
        __syncthreads();
    }

    #pragma unroll
    for (int i = 0; i < 8; i++) {
        int row = rowBase + tr * 8 + i;
        if (row >= nrows) break;
        float s = dinv[row];
        #pragma unroll
        for (int j = 0; j < 8; j += 4) {
            float4 v = make_float4(acc[i][j] * s, acc[i][j + 1] * s,
                                   acc[i][j + 2] * s, acc[i][j + 3] * s);
            *(float4*)&T  [(size_t)row * 128 + tc * 8 + j] = v;
            *(float4*)&AGG[(size_t)row * 128 + tc * 8 + j] = v;
        }
    }
}

// ---------------- edge scatter (HID=128): one warp per edge ----------------
// Each lane loads float4 of the source row and does 4 scalar RED.E.ADD.F32.
__global__ void k_scatter128(const int* __restrict__ ei,
                             const float* __restrict__ T, float* __restrict__ AGG, int E)
{
    int gid  = blockIdx.x * blockDim.x + threadIdx.x;
    int warp = gid >> 5;
    int lane = threadIdx.x & 31;
    if (warp >= E) return;
    int s = ei[warp];
    int d = ei[E + warp];
    float4 v = *(const float4*)&T[(size_t)s * 128 + lane * 4];
    float* dp = &AGG[(size_t)d * 128 + lane * 4];
    atomicAdd(dp + 0, v.x);
    atomicAdd(dp + 1, v.y);
    atomicAdd(dp + 2, v.z);
    atomicAdd(dp + 3, v.w);
}

// ---------------- BN stats ----------------
__global__ void k_zero_stats() {
    g_sum[threadIdx.x] = 0.f;
    g_sq [threadIdx.x] = 0.f;
}

// thread f (of 128) reduces rows [blockIdx.x*128, +128) for feature f; coalesced.
__global__ __launch_bounds__(128) void k_stats(const float* __restrict__ AGG,
                                               const float* __restrict__ dinv,
                                               const float* __restrict__ b, int nrows)
{
    int f  = threadIdx.x;
    int r0 = blockIdx.x * 128;
    int r1 = min(r0 + 128, nrows);
    float bb = b[f];
    float s = 0.f, q = 0.f;
    for (int r = r0; r < r1; r++) {
        float u = dinv[r] * AGG[(size_t)r * 128 + f] + bb;
        s += u; q += u * u;
    }
    atomicAdd(&g_sum[f], s);
    atomicAdd(&g_sq [f], q);
}

__global__ void k_finalize_stats(int nrows) {
    int f = threadIdx.x;
    float inv_n = 1.0f / (float)nrows;
    float m = g_sum[f] * inv_n;
    float v = g_sq[f] * inv_n - m * m;
    g_mean[f] = m;
    g_istd[f] = rsqrtf(v + EPSB);
}

// ---------------- fused (dinv*agg + b) -> BN -> ReLU ----------------
__global__ void k_bnrelu(const float* __restrict__ AGG, const float* __restrict__ dinv,
                         const float* __restrict__ b, const float* __restrict__ g,
                         const float* __restrict__ be, float* __restrict__ H, int nrows)
{
    int idx = blockIdx.x * blockDim.x + threadIdx.x;
    if (idx >= nrows * 128) return;
    int f = idx & 127;
    int r = idx >> 7;
    float u = dinv[r] * AGG[idx] + b[f];
    float h = (u - g_mean[f]) * g_istd[f] * g[f] + be[f];
    H[idx] = fmaxf(h, 0.f);
}

// ---------------- layer-3 GEMM (128 -> 16): one row per thread, W in smem ----------------
__global__ __launch_bounds__(256) void k_gemm16(const float* __restrict__ A,
                                                const float* __restrict__ W,
                                                const float* __restrict__ dinv,
                                                float* __restrict__ T, float* __restrict__ AGG,
                                                int nrows)
{
    __shared__ float Ws[128][16];
    for (int v = threadIdx.x; v < 128 * 16; v += blockDim.x)
        Ws[v >> 4][v & 15] = W[v];
    __syncthreads();

    int row = blockIdx.x * blockDim.x + threadIdx.x;
    if (row >= nrows) return;
    float acc[16];
    #pragma unroll
    for (int c = 0; c < 16; c++) acc[c] = 0.f;

    const float4* ar = (const float4*)&A[(size_t)row * 128];
    #pragma unroll 4
    for (int k4 = 0; k4 < 32; k4++) {
        float4 x = ar[k4];
        int k = k4 * 4;
        #pragma unroll
        for (int c = 0; c < 16; c++)
            acc[c] += x.x * Ws[k][c] + x.y * Ws[k + 1][c]
                    + x.z * Ws[k + 2][c] + x.w * Ws[k + 3][c];
    }
    float s = dinv[row];
    #pragma unroll
    for (int c = 0; c < 16; c += 4) {
        float4 v = make_float4(acc[c] * s, acc[c + 1] * s, acc[c + 2] * s, acc[c + 3] * s);
        *(float4*)&T  [(size_t)row * 16 + c] = v;
        *(float4*)&AGG[(size_t)row * 16 + c] = v;
    }
}

// ---------------- edge scatter (OUTD=16): 4 threads per edge ----------------
__global__ void k_scatter16(const int* __restrict__ ei,
                            const float* __restrict__ T, float* __restrict__ AGG, int E)
{
    int idx = blockIdx.x * blockDim.x + threadIdx.x;
    int e = idx >> 2, p = idx & 3;
    if (e >= E) return;
    int s = ei[e];
    int d = ei[E + e];
    float4 v = *(const float4*)&T[(size_t)s * 16 + p * 4];
    float* dp = &AGG[(size_t)d * 16 + p * 4];
    atomicAdd(dp + 0, v.x);
    atomicAdd(dp + 1, v.y);
    atomicAdd(dp + 2, v.z);
    atomicAdd(dp + 3, v.w);
}

// ---------------- final: out = dinv*agg3 + b3 ----------------
__global__ void k_final(const float* __restrict__ AGG, const float* __restrict__ dinv,
                        const float* __restrict__ b3, float* __restrict__ out, int nrows)
{
    int idx = blockIdx.x * blockDim.x + threadIdx.x;
    if (idx >= nrows * 16) return;
    int r = idx >> 4, f = idx & 15;
    out[idx] = dinv[r] * AGG[idx] + b3[f];
}

// ---------------- launch ----------------
extern "C" void kernel_launch(void* const* d_in, const int* in_sizes, int n_in,
                              void* d_out, int out_size)
{
    const float* x   = (const float*)d_in[0];
    const int*   ei  = (const int*)d_in[1];   // int32 edge_index (JAX downcasts int64 -> int32)
    const float* W1  = (const float*)d_in[2];
    const float* b1  = (const float*)d_in[3];
    const float* g1  = (const float*)d_in[4];
    const float* be1 = (const float*)d_in[5];
    const float* W2  = (const float*)d_in[6];
    const float* b2  = (const float*)d_in[7];
    const float* g2  = (const float*)d_in[8];
    const float* be2 = (const float*)d_in[9];
    const float* W3  = (const float*)d_in[10];
    const float* b3  = (const float*)d_in[11];
    float*       out = (float*)d_out;

    int n = in_sizes[0] / IN_DIM;   // 50000
    int E = in_sizes[1] / 2;        // 800000

    float *deg, *dinv, *bufA, *bufB, *bufC;
    cudaGetSymbolAddress((void**)&deg,  g_deg);
    cudaGetSymbolAddress((void**)&dinv, g_dinv);
    cudaGetSymbolAddress((void**)&bufA, g_bufA);
    cudaGetSymbolAddress((void**)&bufB, g_bufB);
    cudaGetSymbolAddress((void**)&bufC, g_bufC);

    const int T256 = 256;
    int nb_n    = (n + T256 - 1) / T256;
    int nb_e    = (E + T256 - 1) / T256;
    int nb_rows = (n + 127) / 128;          // 391
    int nb_el   = (n * 128 + T256 - 1) / T256;
    long long sc_threads = (long long)E * 32;
    int nb_sc   = (int)((sc_threads + T256 - 1) / T256);   // warp per edge
    int nb_s16  = (E * 4 + T256 - 1) / T256;
    int nb_f    = (n * 16 + T256 - 1) / T256;

    // degree + dinv
    k_init_deg <<<nb_n, T256>>>(deg, n);
    k_count_deg<<<nb_e, T256>>>(ei, deg, E);
    k_dinv     <<<nb_n, T256>>>(deg, dinv, n);

    // ---- layer 1 ----
    k_gemm128   <<<nb_rows, 256>>>(x, W1, dinv, bufA, bufB, n, IN_DIM);
    k_scatter128<<<nb_sc, T256>>>(ei, bufA, bufB, E);
    k_zero_stats<<<1, 128>>>();
    k_stats     <<<nb_rows, 128>>>(bufB, dinv, b1, n);
    k_finalize_stats<<<1, 128>>>(n);
    k_bnrelu    <<<nb_el, T256>>>(bufB, dinv, b1, g1, be1, bufC, n);

    // ---- layer 2 ----
    k_gemm128   <<<nb_rows, 256>>>(bufC, W2, dinv, bufA, bufB, n, HID);
    k_scatter128<<<nb_sc, T256>>>(ei, bufA, bufB, E);
    k_zero_stats<<<1, 128>>>();
    k_stats     <<<nb_rows, 128>>>(bufB, dinv, b2, n);
    k_finalize_stats<<<1, 128>>>(n);
    k_bnrelu    <<<nb_el, T256>>>(bufB, dinv, b2, g2, be2, bufC, n);

    // ---- layer 3 (128 -> 16, no BN) ----
    k_gemm16   <<<nb_n, 256>>>(bufC, W3, dinv, bufA, bufB, n);
    k_scatter16<<<nb_s16, T256>>>(ei, bufA, bufB, E);
    k_final    <<<nb_f, T256>>>(bufB, dinv, b3, out, n);
}

// round 5
// speedup vs baseline: 1.6205x; 1.6205x over previous
#include <cuda_runtime.h>
#include <cstdint>

#define NNODES 50000
#define MAXE   800000
#define IN_DIM 256
#define HID    128
#define OUTD   16
#define EPSB   1e-5f

// ---------------- scratch (static device globals; no allocation) ----------------
__device__ float g_deg [NNODES];
__device__ float g_dinv[NNODES];
__device__ float g_bufA[(size_t)NNODES * HID]; // t  (dinv-scaled h@W)
__device__ float g_bufB[(size_t)NNODES * HID]; // agg (scatter target); also agg3 (first N*16)
__device__ float g_bufC[(size_t)NNODES * HID]; // h  (post BN+ReLU)
__device__ float g_sum [HID];
__device__ float g_sq  [HID];
__device__ float g_mean[HID];
__device__ float g_istd[HID];

__device__ __forceinline__ void red_add_v4(float* p, float4 v) {
    asm volatile("red.global.add.v4.f32 [%0], {%1,%2,%3,%4};"
                 :: "l"(p), "f"(v.x), "f"(v.y), "f"(v.z), "f"(v.w) : "memory");
}

// ---------------- degree / dinv ----------------
__global__ void k_init_deg(float* deg, int n) {
    int i = blockIdx.x * blockDim.x + threadIdx.x;
    if (i < n) deg[i] = 1.0f;  // self-loop
}

__global__ void k_count_deg(const int* __restrict__ ei, float* deg, int E) {
    int i = blockIdx.x * blockDim.x + threadIdx.x;
    if (i < E) {
        int d = ei[E + i];  // dst row
        atomicAdd(&deg[d], 1.0f);
    }
}

__global__ void k_dinv(const float* __restrict__ deg, float* dinv, int n) {
    int i = blockIdx.x * blockDim.x + threadIdx.x;
    if (i < n) dinv[i] = rsqrtf(deg[i]);  // deg >= 1 always
}

// ---------------- SGEMM: T = dinv .* (A @ W), AGG = T  (Ncols = 128) ----------------
// BM=128, BN=128, BK=16, 256 threads, 8x8 micro-tile.
__global__ __launch_bounds__(256) void k_gemm128(
    const float* __restrict__ A, const float* __restrict__ W,
    const float* __restrict__ dinv, float* __restrict__ T, float* __restrict__ AGG,
    int nrows, int K)
{
    __shared__ float As[16][128];
    __shared__ float Bs[16][128];
    int tid = threadIdx.x;
    int tr = tid >> 4;        // 0..15  (row group)
    int tc = tid & 15;        // 0..15  (col group)
    int rowBase = blockIdx.x * 128;

    float acc[8][8];
    #pragma unroll
    for (int i = 0; i < 8; i++)
        #pragma unroll
        for (int j = 0; j < 8; j++) acc[i][j] = 0.f;

    for (int k0 = 0; k0 < K; k0 += 16) {
        // A tile: 128 rows x 16 k, stored transposed As[k][m]
        #pragma unroll
        for (int v = tid; v < 512; v += 256) {
            int r  = v >> 2;
            int c4 = (v & 3) << 2;
            int row = rowBase + r;
            float4 val = make_float4(0.f, 0.f, 0.f, 0.f);
            if (row < nrows) val = *(const float4*)&A[(size_t)row * K + k0 + c4];
            As[c4 + 0][r] = val.x; As[c4 + 1][r] = val.y;
            As[c4 + 2][r] = val.z; As[c4 + 3][r] = val.w;
        }
        // W tile: 16 k x 128 n, row-major
        #pragma unroll
        for (int v = tid; v < 512; v += 256) {
            int kk = v >> 5;
            int c4 = (v & 31) << 2;
            *(float4*)&Bs[kk][c4] = *(const float4*)&W[(size_t)(k0 + kk) * 128 + c4];
        }
        __syncthreads();

        #pragma unroll
        for (int kk = 0; kk < 16; kk++) {
            float4 m0 = *(float4*)&As[kk][tr * 8];
            float4 m1 = *(float4*)&As[kk][tr * 8 + 4];
            float4 n0 = *(float4*)&Bs[kk][tc * 8];
            float4 n1 = *(float4*)&Bs[kk][tc * 8 + 4];
            float rm[8] = {m0.x, m0.y, m0.z, m0.w, m1.x, m1.y, m1.z, m1.w};
            float rn[8] = {n0.x, n0.y, n0.z, n0.w, n1.x, n1.y, n1.z, n1.w};
            #pragma unroll
            for (int i = 0; i < 8; i++)
                #pragma unroll
                for (int j = 0; j < 8; j++)
                    acc[i][j] += rm[i] * rn[j];
        }
        __syncthreads();
    }

    #pragma unroll
    for (int i = 0; i < 8; i++) {
        int row = rowBase + tr * 8 + i;
        if (row >= nrows) break;
        float s = dinv[row];
        #pragma unroll
        for (int j = 0; j < 8; j += 4) {
            float4 v = make_float4(acc[i][j] * s, acc[i][j + 1] * s,
                                   acc[i][j + 2] * s, acc[i][j + 3] * s);
            *(float4*)&T  [(size_t)row * 128 + tc * 8 + j] = v;
            *(float4*)&AGG[(size_t)row * 128 + tc * 8 + j] = v;
        }
    }
}

// ---------------- edge scatter (HID=128): one warp per edge ----------------
// Each lane loads float4 of the source row and issues ONE red.global.add.v4.f32.
__global__ void k_scatter128(const int* __restrict__ ei,
                             const float* __restrict__ T, float* __restrict__ AGG, int E)
{
    int gid  = blockIdx.x * blockDim.x + threadIdx.x;
    int warp = gid >> 5;
    int lane = threadIdx.x & 31;
    if (warp >= E) return;
    int s = ei[warp];
    int d = ei[E + warp];
    float4 v = *(const float4*)&T[(size_t)s * 128 + lane * 4];
    red_add_v4(&AGG[(size_t)d * 128 + lane * 4], v);
}

// ---------------- BN stats ----------------
__global__ void k_zero_stats() {
    g_sum[threadIdx.x] = 0.f;
    g_sq [threadIdx.x] = 0.f;
}

// thread f (of 128) reduces rows [blockIdx.x*128, +128) for feature f; coalesced.
__global__ __launch_bounds__(128) void k_stats(const float* __restrict__ AGG,
                                               const float* __restrict__ dinv,
                                               const float* __restrict__ b, int nrows)
{
    int f  = threadIdx.x;
    int r0 = blockIdx.x * 128;
    int r1 = min(r0 + 128, nrows);
    float bb = b[f];
    float s = 0.f, q = 0.f;
    for (int r = r0; r < r1; r++) {
        float u = dinv[r] * AGG[(size_t)r * 128 + f] + bb;
        s += u; q += u * u;
    }
    atomicAdd(&g_sum[f], s);
    atomicAdd(&g_sq [f], q);
}

__global__ void k_finalize_stats(int nrows) {
    int f = threadIdx.x;
    float inv_n = 1.0f / (float)nrows;
    float m = g_sum[f] * inv_n;
    float v = g_sq[f] * inv_n - m * m;
    g_mean[f] = m;
    g_istd[f] = rsqrtf(v + EPSB);
}

// ---------------- fused (dinv*agg + b) -> BN -> ReLU ----------------
__global__ void k_bnrelu(const float* __restrict__ AGG, const float* __restrict__ dinv,
                         const float* __restrict__ b, const float* __restrict__ g,
                         const float* __restrict__ be, float* __restrict__ H, int nrows)
{
    int idx = blockIdx.x * blockDim.x + threadIdx.x;
    if (idx >= nrows * 128) return;
    int f = idx & 127;
    int r = idx >> 7;
    float u = dinv[r] * AGG[idx] + b[f];
    float h = (u - g_mean[f]) * g_istd[f] * g[f] + be[f];
    H[idx] = fmaxf(h, 0.f);
}

// ---------------- layer-3 GEMM (128 -> 16): one row per thread, W in smem ----------------
__global__ __launch_bounds__(256) void k_gemm16(const float* __restrict__ A,
                                                const float* __restrict__ W,
                                                const float* __restrict__ dinv,
                                                float* __restrict__ T, float* __restrict__ AGG,
                                                int nrows)
{
    __shared__ float Ws[128][16];
    for (int v = threadIdx.x; v < 128 * 16; v += blockDim.x)
        Ws[v >> 4][v & 15] = W[v];
    __syncthreads();

    int row = blockIdx.x * blockDim.x + threadIdx.x;
    if (row >= nrows) return;
    float acc[16];
    #pragma unroll
    for (int c = 0; c < 16; c++) acc[c] = 0.f;

    const float4* ar = (const float4*)&A[(size_t)row * 128];
    #pragma unroll 4
    for (int k4 = 0; k4 < 32; k4++) {
        float4 x = ar[k4];
        int k = k4 * 4;
        #pragma unroll
        for (int c = 0; c < 16; c++)
            acc[c] += x.x * Ws[k][c] + x.y * Ws[k + 1][c]
                    + x.z * Ws[k + 2][c] + x.w * Ws[k + 3][c];
    }
    float s = dinv[row];
    #pragma unroll
    for (int c = 0; c < 16; c += 4) {
        float4 v = make_float4(acc[c] * s, acc[c + 1] * s, acc[c + 2] * s, acc[c + 3] * s);
        *(float4*)&T  [(size_t)row * 16 + c] = v;
        *(float4*)&AGG[(size_t)row * 16 + c] = v;
    }
}

// ---------------- edge scatter (OUTD=16): 4 threads per edge ----------------
__global__ void k_scatter16(const int* __restrict__ ei,
                            const float* __restrict__ T, float* __restrict__ AGG, int E)
{
    int idx = blockIdx.x * blockDim.x + threadIdx.x;
    int e = idx >> 2, p = idx & 3;
    if (e >= E) return;
    int s = ei[e];
    int d = ei[E + e];
    float4 v = *(const float4*)&T[(size_t)s * 16 + p * 4];
    red_add_v4(&AGG[(size_t)d * 16 + p * 4], v);
}

// ---------------- final: out = dinv*agg3 + b3 ----------------
__global__ void k_final(const float* __restrict__ AGG, const float* __restrict__ dinv,
                        const float* __restrict__ b3, float* __restrict__ out, int nrows)
{
    int idx = blockIdx.x * blockDim.x + threadIdx.x;
    if (idx >= nrows * 16) return;
    int r = idx >> 4, f = idx & 15;
    out[idx] = dinv[r] * AGG[idx] + b3[f];
}

// ---------------- launch ----------------
extern "C" void kernel_launch(void* const* d_in, const int* in_sizes, int n_in,
                              void* d_out, int out_size)
{
    const float* x   = (const float*)d_in[0];
    const int*   ei  = (const int*)d_in[1];   // int32 edge_index
    const float* W1  = (const float*)d_in[2];
    const float* b1  = (const float*)d_in[3];
    const float* g1  = (const float*)d_in[4];
    const float* be1 = (const float*)d_in[5];
    const float* W2  = (const float*)d_in[6];
    const float* b2  = (const float*)d_in[7];
    const float* g2  = (const float*)d_in[8];
    const float* be2 = (const float*)d_in[9];
    const float* W3  = (const float*)d_in[10];
    const float* b3  = (const float*)d_in[11];
    float*       out = (float*)d_out;

    int n = in_sizes[0] / IN_DIM;   // 50000
    int E = in_sizes[1] / 2;        // 800000

    float *deg, *dinv, *bufA, *bufB, *bufC;
    cudaGetSymbolAddress((void**)&deg,  g_deg);
    cudaGetSymbolAddress((void**)&dinv, g_dinv);
    cudaGetSymbolAddress((void**)&bufA, g_bufA);
    cudaGetSymbolAddress((void**)&bufB, g_bufB);
    cudaGetSymbolAddress((void**)&bufC, g_bufC);

    const int T256 = 256;
    int nb_n    = (n + T256 - 1) / T256;
    int nb_e    = (E + T256 - 1) / T256;
    int nb_rows = (n + 127) / 128;          // 391
    int nb_el   = (n * 128 + T256 - 1) / T256;
    long long sc_threads = (long long)E * 32;
    int nb_sc   = (int)((sc_threads + T256 - 1) / T256);   // warp per edge
    int nb_s16  = (E * 4 + T256 - 1) / T256;
    int nb_f    = (n * 16 + T256 - 1) / T256;

    // degree + dinv
    k_init_deg <<<nb_n, T256>>>(deg, n);
    k_count_deg<<<nb_e, T256>>>(ei, deg, E);
    k_dinv     <<<nb_n, T256>>>(deg, dinv, n);

    // ---- layer 1 ----
    k_gemm128   <<<nb_rows, 256>>>(x, W1, dinv, bufA, bufB, n, IN_DIM);
    k_scatter128<<<nb_sc, T256>>>(ei, bufA, bufB, E);
    k_zero_stats<<<1, 128>>>();
    k_stats     <<<nb_rows, 128>>>(bufB, dinv, b1, n);
    k_finalize_stats<<<1, 128>>>(n);
    k_bnrelu    <<<nb_el, T256>>>(bufB, dinv, b1, g1, be1, bufC, n);

    // ---- layer 2 ----
    k_gemm128   <<<nb_rows, 256>>>(bufC, W2, dinv, bufA, bufB, n, HID);
    k_scatter128<<<nb_sc, T256>>>(ei, bufA, bufB, E);
    k_zero_stats<<<1, 128>>>();
    k_stats     <<<nb_rows, 128>>>(bufB, dinv, b2, n);
    k_finalize_stats<<<1, 128>>>(n);
    k_bnrelu    <<<nb_el, T256>>>(bufB, dinv, b2, g2, be2, bufC, n);

    // ---- layer 3 (128 -> 16, no BN) ----
    k_gemm16   <<<nb_n, 256>>>(bufC, W3, dinv, bufA, bufB, n);
    k_scatter16<<<nb_s16, T256>>>(ei, bufA, bufB, E);
    k_final    <<<nb_f, T256>>>(bufB, dinv, b3, out, n);
}

// round 6
// speedup vs baseline: 1.7793x; 1.0980x over previous
#include <cuda_runtime.h>
#include <cstdint>

#define NNODES 50000
#define MAXE   800000
#define IN_DIM 256
#define HID    128
#define OUTD   16
#define EPSB   1e-5f

// ---------------- scratch (static device globals; no allocation) ----------------
__device__ float g_deg [NNODES];
__device__ float g_dinv[NNODES];
__device__ float g_bufA[(size_t)NNODES * HID]; // t  (dinv-scaled h@W)
__device__ float g_bufB[(size_t)NNODES * HID]; // agg (scatter target); also agg3
__device__ float g_bufC[(size_t)NNODES * HID]; // h  (post BN+ReLU)
__device__ float g_sum [HID];
__device__ float g_sq  [HID];
__device__ float g_mean[HID];
__device__ float g_istd[HID];

__device__ __forceinline__ void red_add_v4(float* p, float4 v) {
    asm volatile("red.global.add.v4.f32 [%0], {%1,%2,%3,%4};"
                 :: "l"(p), "f"(v.x), "f"(v.y), "f"(v.z), "f"(v.w) : "memory");
}

__device__ __forceinline__ uint32_t f2tf32(float a) {
    uint32_t r;
    asm("cvt.rna.tf32.f32 %0, %1;" : "=r"(r) : "f"(a));
    return r;
}

__device__ __forceinline__ void mma_tf32(float* d, const uint32_t* a, const uint32_t* b) {
    asm volatile(
        "mma.sync.aligned.m16n8k8.row.col.f32.tf32.tf32.f32 "
        "{%0,%1,%2,%3}, {%4,%5,%6,%7}, {%8,%9}, {%0,%1,%2,%3};"
        : "+f"(d[0]), "+f"(d[1]), "+f"(d[2]), "+f"(d[3])
        : "r"(a[0]), "r"(a[1]), "r"(a[2]), "r"(a[3]), "r"(b[0]), "r"(b[1]));
}

// ---------------- degree / dinv ----------------
__global__ void k_init_deg(float* deg, int n) {
    int i = blockIdx.x * blockDim.x + threadIdx.x;
    if (i < n) deg[i] = 1.0f;  // self-loop
}

__global__ void k_count_deg(const int* __restrict__ ei, float* deg, int E) {
    int i = blockIdx.x * blockDim.x + threadIdx.x;
    if (i < E) {
        int d = ei[E + i];
        atomicAdd(&deg[d], 1.0f);
    }
}

__global__ void k_dinv(const float* __restrict__ deg, float* dinv, int n) {
    int i = blockIdx.x * blockDim.x + threadIdx.x;
    if (i < n) dinv[i] = rsqrtf(deg[i]);
}

// ---------------- TF32 tensor-core GEMM: T = dinv .* (A @ W), AGG = T ----------------
// BM=128, BN=128 (=HID), BK=32. 256 threads = 8 warps (4 warpM x 2 warpN).
// Each warp: 32 rows x 64 cols = 2 m16-tiles x 8 n8-tiles, m16n8k8 tf32 mma.
// Compensated TF32: D = Ah*Wh + Al*Wh + Ah*Wl  (fp32-class accuracy).
__global__ __launch_bounds__(256) void k_gemm_tc(
    const float* __restrict__ A, const float* __restrict__ W,
    const float* __restrict__ dinv, float* __restrict__ T, float* __restrict__ AGG,
    int nrows, int K)
{
    __shared__ float As[128][36];   // [m][k] pad-> conflict-free frags (4m+t distinct)
    __shared__ float Ws[32][136];   // [k][n] pad 136 -> bank = 8t+g distinct

    int tid   = threadIdx.x;
    int lane  = tid & 31;
    int warp  = tid >> 5;
    int warpM = warp >> 1;           // 0..3
    int warpN = warp & 1;            // 0..1
    int g     = lane >> 2;           // 0..7
    int t     = lane & 3;            // 0..3
    int rowBase = blockIdx.x * 128;

    float d[2][8][4];
    #pragma unroll
    for (int mt = 0; mt < 2; mt++)
        #pragma unroll
        for (int nt = 0; nt < 8; nt++)
            #pragma unroll
            for (int i = 0; i < 4; i++) d[mt][nt][i] = 0.f;

    for (int k0 = 0; k0 < K; k0 += 32) {
        // A tile: 128 x 32 (8 float4 per row), 1024 float4 / 256 thr = 4 each
        #pragma unroll
        for (int i = 0; i < 4; i++) {
            int v  = tid + i * 256;
            int r  = v >> 3;
            int c4 = (v & 7) << 2;
            int row = rowBase + r;
            float4 val = make_float4(0.f, 0.f, 0.f, 0.f);
            if (row < nrows) val = *(const float4*)&A[(size_t)row * K + k0 + c4];
            *(float4*)&As[r][c4] = val;
        }
        // W tile: 32 x 128
        #pragma unroll
        for (int i = 0; i < 4; i++) {
            int v  = tid + i * 256;
            int kk = v >> 5;
            int c4 = (v & 31) << 2;
            *(float4*)&Ws[kk][c4] = *(const float4*)&W[(size_t)(k0 + kk) * 128 + c4];
        }
        __syncthreads();

        #pragma unroll
        for (int kc = 0; kc < 32; kc += 8) {
            // A fragments (hi/lo) for both m-tiles
            uint32_t ah[2][4], al[2][4];
            #pragma unroll
            for (int mt = 0; mt < 2; mt++) {
                int m = warpM * 32 + mt * 16 + g;
                float a0 = As[m    ][kc + t];
                float a1 = As[m + 8][kc + t];
                float a2 = As[m    ][kc + t + 4];
                float a3 = As[m + 8][kc + t + 4];
                ah[mt][0] = f2tf32(a0); al[mt][0] = f2tf32(a0 - __uint_as_float(ah[mt][0]));
                ah[mt][1] = f2tf32(a1); al[mt][1] = f2tf32(a1 - __uint_as_float(ah[mt][1]));
                ah[mt][2] = f2tf32(a2); al[mt][2] = f2tf32(a2 - __uint_as_float(ah[mt][2]));
                ah[mt][3] = f2tf32(a3); al[mt][3] = f2tf32(a3 - __uint_as_float(ah[mt][3]));
            }
            #pragma unroll
            for (int nt = 0; nt < 8; nt++) {
                int n = warpN * 64 + nt * 8 + g;
                float b0 = Ws[kc + t    ][n];
                float b1 = Ws[kc + t + 4][n];
                uint32_t bh[2], bl[2];
                bh[0] = f2tf32(b0); bl[0] = f2tf32(b0 - __uint_as_float(bh[0]));
                bh[1] = f2tf32(b1); bl[1] = f2tf32(b1 - __uint_as_float(bh[1]));
                #pragma unroll
                for (int mt = 0; mt < 2; mt++) {
                    mma_tf32(d[mt][nt], ah[mt], bh);
                    mma_tf32(d[mt][nt], al[mt], bh);
                    mma_tf32(d[mt][nt], ah[mt], bl);
                }
            }
        }
        __syncthreads();
    }

    // epilogue: rows r0=base+g, r1=r0+8; cols = warpN*64 + nt*8 + 2t + {0,1}
    #pragma unroll
    for (int mt = 0; mt < 2; mt++) {
        int r0 = rowBase + warpM * 32 + mt * 16 + g;
        int r1 = r0 + 8;
        float s0 = (r0 < nrows) ? dinv[r0] : 0.f;
        float s1 = (r1 < nrows) ? dinv[r1] : 0.f;
        #pragma unroll
        for (int nt = 0; nt < 8; nt++) {
            int c = warpN * 64 + nt * 8 + 2 * t;
            if (r0 < nrows) {
                float2 v0 = make_float2(d[mt][nt][0] * s0, d[mt][nt][1] * s0);
                *(float2*)&T  [(size_t)r0 * 128 + c] = v0;
                *(float2*)&AGG[(size_t)r0 * 128 + c] = v0;
            }
            if (r1 < nrows) {
                float2 v1 = make_float2(d[mt][nt][2] * s1, d[mt][nt][3] * s1);
                *(float2*)&T  [(size_t)r1 * 128 + c] = v1;
                *(float2*)&AGG[(size_t)r1 * 128 + c] = v1;
            }
        }
    }
}

// ---------------- edge scatter (HID=128): one warp per edge, v4 RED ----------------
__global__ void k_scatter128(const int* __restrict__ ei,
                             const float* __restrict__ T, float* __restrict__ AGG, int E)
{
    int gid  = blockIdx.x * blockDim.x + threadIdx.x;
    int warp = gid >> 5;
    int lane = threadIdx.x & 31;
    if (warp >= E) return;
    int s = ei[warp];
    int d = ei[E + warp];
    float4 v = *(const float4*)&T[(size_t)s * 128 + lane * 4];
    red_add_v4(&AGG[(size_t)d * 128 + lane * 4], v);
}

// ---------------- BN stats ----------------
__global__ void k_zero_stats() {
    g_sum[threadIdx.x] = 0.f;
    g_sq [threadIdx.x] = 0.f;
}

__global__ __launch_bounds__(128) void k_stats(const float* __restrict__ AGG,
                                               const float* __restrict__ dinv,
                                               const float* __restrict__ b, int nrows)
{
    int f  = threadIdx.x;
    int r0 = blockIdx.x * 128;
    int r1 = min(r0 + 128, nrows);
    float bb = b[f];
    float s = 0.f, q = 0.f;
    for (int r = r0; r < r1; r++) {
        float u = dinv[r] * AGG[(size_t)r * 128 + f] + bb;
        s += u; q += u * u;
    }
    atomicAdd(&g_sum[f], s);
    atomicAdd(&g_sq [f], q);
}

__global__ void k_finalize_stats(int nrows) {
    int f = threadIdx.x;
    float inv_n = 1.0f / (float)nrows;
    float m = g_sum[f] * inv_n;
    float v = g_sq[f] * inv_n - m * m;
    g_mean[f] = m;
    g_istd[f] = rsqrtf(v + EPSB);
}

// ---------------- fused (dinv*agg + b) -> BN -> ReLU ----------------
__global__ void k_bnrelu(const float* __restrict__ AGG, const float* __restrict__ dinv,
                         const float* __restrict__ b, const float* __restrict__ g,
                         const float* __restrict__ be, float* __restrict__ H, int nrows)
{
    int idx = blockIdx.x * blockDim.x + threadIdx.x;
    if (idx >= nrows * 128) return;
    int f = idx & 127;
    int r = idx >> 7;
    float u = dinv[r] * AGG[idx] + b[f];
    float h = (u - g_mean[f]) * g_istd[f] * g[f] + be[f];
    H[idx] = fmaxf(h, 0.f);
}

// ---------------- layer-3 GEMM (128 -> 16): one row per thread, W in smem ----------------
__global__ __launch_bounds__(256) void k_gemm16(const float* __restrict__ A,
                                                const float* __restrict__ W,
                                                const float* __restrict__ dinv,
                                                float* __restrict__ T, float* __restrict__ AGG,
                                                int nrows)
{
    __shared__ float Ws[128][16];
    for (int v = threadIdx.x; v < 128 * 16; v += blockDim.x)
        Ws[v >> 4][v & 15] = W[v];
    __syncthreads();

    int row = blockIdx.x * blockDim.x + threadIdx.x;
    if (row >= nrows) return;
    float acc[16];
    #pragma unroll
    for (int c = 0; c < 16; c++) acc[c] = 0.f;

    const float4* ar = (const float4*)&A[(size_t)row * 128];
    #pragma unroll 4
    for (int k4 = 0; k4 < 32; k4++) {
        float4 x = ar[k4];
        int k = k4 * 4;
        #pragma unroll
        for (int c = 0; c < 16; c++)
            acc[c] += x.x * Ws[k][c] + x.y * Ws[k + 1][c]
                    + x.z * Ws[k + 2][c] + x.w * Ws[k + 3][c];
    }
    float s = dinv[row];
    #pragma unroll
    for (int c = 0; c < 16; c += 4) {
        float4 v = make_float4(acc[c] * s, acc[c + 1] * s, acc[c + 2] * s, acc[c + 3] * s);
        *(float4*)&T  [(size_t)row * 16 + c] = v;
        *(float4*)&AGG[(size_t)row * 16 + c] = v;
    }
}

// ---------------- edge scatter (OUTD=16): 4 threads per edge ----------------
__global__ void k_scatter16(const int* __restrict__ ei,
                            const float* __restrict__ T, float* __restrict__ AGG, int E)
{
    int idx = blockIdx.x * blockDim.x + threadIdx.x;
    int e = idx >> 2, p = idx & 3;
    if (e >= E) return;
    int s = ei[e];
    int d = ei[E + e];
    float4 v = *(const float4*)&T[(size_t)s * 16 + p * 4];
    red_add_v4(&AGG[(size_t)d * 16 + p * 4], v);
}

// ---------------- final: out = dinv*agg3 + b3 ----------------
__global__ void k_final(const float* __restrict__ AGG, const float* __restrict__ dinv,
                        const float* __restrict__ b3, float* __restrict__ out, int nrows)
{
    int idx = blockIdx.x * blockDim.x + threadIdx.x;
    if (idx >= nrows * 16) return;
    int r = idx >> 4, f = idx & 15;
    out[idx] = dinv[r] * AGG[idx] + b3[f];
}

// ---------------- launch ----------------
extern "C" void kernel_launch(void* const* d_in, const int* in_sizes, int n_in,
                              void* d_out, int out_size)
{
    const float* x   = (const float*)d_in[0];
    const int*   ei  = (const int*)d_in[1];   // int32 edge_index
    const float* W1  = (const float*)d_in[2];
    const float* b1  = (const float*)d_in[3];
    const float* g1  = (const float*)d_in[4];
    const float* be1 = (const float*)d_in[5];
    const float* W2  = (const float*)d_in[6];
    const float* b2  = (const float*)d_in[7];
    const float* g2  = (const float*)d_in[8];
    const float* be2 = (const float*)d_in[9];
    const float* W3  = (const float*)d_in[10];
    const float* b3  = (const float*)d_in[11];
    float*       out = (float*)d_out;

    int n = in_sizes[0] / IN_DIM;   // 50000
    int E = in_sizes[1] / 2;        // 800000

    float *deg, *dinv, *bufA, *bufB, *bufC;
    cudaGetSymbolAddress((void**)&deg,  g_deg);
    cudaGetSymbolAddress((void**)&dinv, g_dinv);
    cudaGetSymbolAddress((void**)&bufA, g_bufA);
    cudaGetSymbolAddress((void**)&bufB, g_bufB);
    cudaGetSymbolAddress((void**)&bufC, g_bufC);

    const int T256 = 256;
    int nb_n    = (n + T256 - 1) / T256;
    int nb_e    = (E + T256 - 1) / T256;
    int nb_rows = (n + 127) / 128;          // 391
    int nb_el   = (n * 128 + T256 - 1) / T256;
    long long sc_threads = (long long)E * 32;
    int nb_sc   = (int)((sc_threads + T256 - 1) / T256);   // warp per edge
    int nb_s16  = (E * 4 + T256 - 1) / T256;
    int nb_f    = (n * 16 + T256 - 1) / T256;

    // degree + dinv
    k_init_deg <<<nb_n, T256>>>(deg, n);
    k_count_deg<<<nb_e, T256>>>(ei, deg, E);
    k_dinv     <<<nb_n, T256>>>(deg, dinv, n);

    // ---- layer 1 ----
    k_gemm_tc   <<<nb_rows, 256>>>(x, W1, dinv, bufA, bufB, n, IN_DIM);
    k_scatter128<<<nb_sc, T256>>>(ei, bufA, bufB, E);
    k_zero_stats<<<1, 128>>>();
    k_stats     <<<nb_rows, 128>>>(bufB, dinv, b1, n);
    k_finalize_stats<<<1, 128>>>(n);
    k_bnrelu    <<<nb_el, T256>>>(bufB, dinv, b1, g1, be1, bufC, n);

    // ---- layer 2 ----
    k_gemm_tc   <<<nb_rows, 256>>>(bufC, W2, dinv, bufA, bufB, n, HID);
    k_scatter128<<<nb_sc, T256>>>(ei, bufA, bufB, E);
    k_zero_stats<<<1, 128>>>();
    k_stats     <<<nb_rows, 128>>>(bufB, dinv, b2, n);
    k_finalize_stats<<<1, 128>>>(n);
    k_bnrelu    <<<nb_el, T256>>>(bufB, dinv, b2, g2, be2, bufC, n);

    // ---- layer 3 (128 -> 16, no BN) ----
    k_gemm16   <<<nb_n, 256>>>(bufC, W3, dinv, bufA, bufB, n);
    k_scatter16<<<nb_s16, T256>>>(ei, bufA, bufB, E);
    k_final    <<<nb_f, T256>>>(bufB, dinv, b3, out, n);
}

// round 7
// speedup vs baseline: 1.7794x; 1.0001x over previous
#include <cuda_runtime.h>
#include <cstdint>

#define NNODES 50000
#define MAXE   800000
#define IN_DIM 256
#define HID    128
#define OUTD   16
#define EPSB   1e-5f

// ---------------- scratch (static device globals; no allocation) ----------------
__device__ int   g_cnt   [NNODES];
__device__ int   g_rowptr[NNODES + 1];
__device__ int   g_cursor[NNODES];
__device__ int   g_col   [MAXE];
__device__ float g_dinv  [NNODES];
__device__ float g_bufA[(size_t)NNODES * HID]; // t (dinv-scaled h@W)
__device__ float g_bufB[(size_t)NNODES * HID]; // u (post-aggregation, pre-BN)
__device__ float g_bufC[(size_t)NNODES * HID]; // h (post BN+ReLU)
__device__ float g_sum [HID];
__device__ float g_sq  [HID];
__device__ float g_mean[HID];
__device__ float g_istd[HID];

__device__ __forceinline__ uint32_t f2tf32(float a) {
    uint32_t r;
    asm("cvt.rna.tf32.f32 %0, %1;" : "=r"(r) : "f"(a));
    return r;
}

__device__ __forceinline__ void mma_tf32(float* d, const uint32_t* a, const uint32_t* b) {
    asm volatile(
        "mma.sync.aligned.m16n8k8.row.col.f32.tf32.tf32.f32 "
        "{%0,%1,%2,%3}, {%4,%5,%6,%7}, {%8,%9}, {%0,%1,%2,%3};"
        : "+f"(d[0]), "+f"(d[1]), "+f"(d[2]), "+f"(d[3])
        : "r"(a[0]), "r"(a[1]), "r"(a[2]), "r"(a[3]), "r"(b[0]), "r"(b[1]));
}

// ---------------- CSR build ----------------
__global__ void k_zero_cnt(int* cnt, int n) {
    int i = blockIdx.x * blockDim.x + threadIdx.x;
    if (i < n) cnt[i] = 0;
}

__global__ void k_hist(const int* __restrict__ ei, int* cnt, int E) {
    int i = blockIdx.x * blockDim.x + threadIdx.x;
    if (i < E) atomicAdd(&cnt[ei[E + i]], 1);
}

// single block, 1024 threads: exclusive scan of cnt -> rowptr & cursor; dinv.
__global__ __launch_bounds__(1024) void k_scan(const int* __restrict__ cnt,
                                               int* rowptr, int* cursor,
                                               float* dinv, int n)
{
    __shared__ int part[1024];
    int tid = threadIdx.x;
    int chunk = (n + 1023) >> 10;
    int lo = tid * chunk, hi = min(lo + chunk, n);
    int s = 0;
    for (int i = lo; i < hi; i++) s += cnt[i];
    part[tid] = s;
    __syncthreads();
    for (int off = 1; off < 1024; off <<= 1) {
        int v = 0;
        if (tid >= off) v = part[tid - off];
        __syncthreads();
        if (tid >= off) part[tid] += v;
        __syncthreads();
    }
    int run = (tid > 0) ? part[tid - 1] : 0;
    for (int i = lo; i < hi; i++) {
        rowptr[i] = run;
        cursor[i] = run;
        dinv[i] = rsqrtf((float)cnt[i] + 1.0f);  // self-loop included
        run += cnt[i];
    }
    if (tid == 1023) rowptr[n] = part[1023];
}

__global__ void k_fill(const int* __restrict__ ei, int* cursor, int* col, int E) {
    int i = blockIdx.x * blockDim.x + threadIdx.x;
    if (i < E) {
        int d = ei[E + i];
        int p = atomicAdd(&cursor[d], 1);
        col[p] = ei[i];  // src
    }
}

// ---------------- TF32 tensor-core GEMM: T = dinv .* (A @ W)  (BN=128) ----------------
__global__ __launch_bounds__(256) void k_gemm_tc(
    const float* __restrict__ A, const float* __restrict__ W,
    const float* __restrict__ dinv, float* __restrict__ T,
    int nrows, int K)
{
    __shared__ float As[128][36];
    __shared__ float Ws[32][136];

    int tid   = threadIdx.x;
    int lane  = tid & 31;
    int warp  = tid >> 5;
    int warpM = warp >> 1;
    int warpN = warp & 1;
    int g     = lane >> 2;
    int t     = lane & 3;
    int rowBase = blockIdx.x * 128;

    float d[2][8][4];
    #pragma unroll
    for (int mt = 0; mt < 2; mt++)
        #pragma unroll
        for (int nt = 0; nt < 8; nt++)
            #pragma unroll
            for (int i = 0; i < 4; i++) d[mt][nt][i] = 0.f;

    for (int k0 = 0; k0 < K; k0 += 32) {
        #pragma unroll
        for (int i = 0; i < 4; i++) {
            int v  = tid + i * 256;
            int r  = v >> 3;
            int c4 = (v & 7) << 2;
            int row = rowBase + r;
            float4 val = make_float4(0.f, 0.f, 0.f, 0.f);
            if (row < nrows) val = *(const float4*)&A[(size_t)row * K + k0 + c4];
            *(float4*)&As[r][c4] = val;
        }
        #pragma unroll
        for (int i = 0; i < 4; i++) {
            int v  = tid + i * 256;
            int kk = v >> 5;
            int c4 = (v & 31) << 2;
            *(float4*)&Ws[kk][c4] = *(const float4*)&W[(size_t)(k0 + kk) * 128 + c4];
        }
        __syncthreads();

        #pragma unroll
        for (int kc = 0; kc < 32; kc += 8) {
            uint32_t ah[2][4], al[2][4];
            #pragma unroll
            for (int mt = 0; mt < 2; mt++) {
                int m = warpM * 32 + mt * 16 + g;
                float a0 = As[m    ][kc + t];
                float a1 = As[m + 8][kc + t];
                float a2 = As[m    ][kc + t + 4];
                float a3 = As[m + 8][kc + t + 4];
                ah[mt][0] = f2tf32(a0); al[mt][0] = f2tf32(a0 - __uint_as_float(ah[mt][0]));
                ah[mt][1] = f2tf32(a1); al[mt][1] = f2tf32(a1 - __uint_as_float(ah[mt][1]));
                ah[mt][2] = f2tf32(a2); al[mt][2] = f2tf32(a2 - __uint_as_float(ah[mt][2]));
                ah[mt][3] = f2tf32(a3); al[mt][3] = f2tf32(a3 - __uint_as_float(ah[mt][3]));
            }
            #pragma unroll
            for (int nt = 0; nt < 8; nt++) {
                int n = warpN * 64 + nt * 8 + g;
                float b0 = Ws[kc + t    ][n];
                float b1 = Ws[kc + t + 4][n];
                uint32_t bh[2], bl[2];
                bh[0] = f2tf32(b0); bl[0] = f2tf32(b0 - __uint_as_float(bh[0]));
                bh[1] = f2tf32(b1); bl[1] = f2tf32(b1 - __uint_as_float(bh[1]));
                #pragma unroll
                for (int mt = 0; mt < 2; mt++) {
                    mma_tf32(d[mt][nt], ah[mt], bh);
                    mma_tf32(d[mt][nt], al[mt], bh);
                    mma_tf32(d[mt][nt], ah[mt], bl);
                }
            }
        }
        __syncthreads();
    }

    #pragma unroll
    for (int mt = 0; mt < 2; mt++) {
        int r0 = rowBase + warpM * 32 + mt * 16 + g;
        int r1 = r0 + 8;
        float s0 = (r0 < nrows) ? dinv[r0] : 0.f;
        float s1 = (r1 < nrows) ? dinv[r1] : 0.f;
        #pragma unroll
        for (int nt = 0; nt < 8; nt++) {
            int c = warpN * 64 + nt * 8 + 2 * t;
            if (r0 < nrows)
                *(float2*)&T[(size_t)r0 * 128 + c] =
                    make_float2(d[mt][nt][0] * s0, d[mt][nt][1] * s0);
            if (r1 < nrows)
                *(float2*)&T[(size_t)r1 * 128 + c] =
                    make_float2(d[mt][nt][2] * s1, d[mt][nt][3] * s1);
        }
    }
}

// ---------------- BN stats helpers ----------------
__global__ void k_zero_stats() {
    g_sum[threadIdx.x] = 0.f;
    g_sq [threadIdx.x] = 0.f;
}

__global__ void k_finalize_stats(int nrows) {
    int f = threadIdx.x;
    float inv_n = 1.0f / (float)nrows;
    float m = g_sum[f] * inv_n;
    float v = g_sq[f] * inv_n - m * m;
    g_mean[f] = m;
    g_istd[f] = rsqrtf(v + EPSB);
}

// ---------------- CSR aggregation (HID=128): warp per node, fused u + stats ----------------
// u = dinv[node] * (T[node] + sum_nbr T[src]) + b ; writes U; accumulates BN stats.
__global__ __launch_bounds__(256) void k_agg128(
    const int* __restrict__ rowptr, const int* __restrict__ col,
    const float* __restrict__ T, const float* __restrict__ dinv,
    const float* __restrict__ b, float* __restrict__ U, int n)
{
    int lane   = threadIdx.x & 31;
    int warp   = (blockIdx.x * blockDim.x + threadIdx.x) >> 5;
    int nwarps = (gridDim.x * blockDim.x) >> 5;
    float4 bb  = *(const float4*)&b[lane * 4];

    float4 s4 = make_float4(0.f, 0.f, 0.f, 0.f);
    float4 q4 = make_float4(0.f, 0.f, 0.f, 0.f);

    for (int node = warp; node < n; node += nwarps) {
        int beg = rowptr[node], end = rowptr[node + 1];
        float4 acc = *(const float4*)&T[(size_t)node * 128 + lane * 4];  // self-loop
        int e = beg;
        for (; e + 3 < end; e += 4) {
            int s0 = col[e], s1 = col[e + 1], s2 = col[e + 2], s3 = col[e + 3];
            float4 v0 = *(const float4*)&T[(size_t)s0 * 128 + lane * 4];
            float4 v1 = *(const float4*)&T[(size_t)s1 * 128 + lane * 4];
            float4 v2 = *(const float4*)&T[(size_t)s2 * 128 + lane * 4];
            float4 v3 = *(const float4*)&T[(size_t)s3 * 128 + lane * 4];
            acc.x += v0.x + v1.x + v2.x + v3.x;
            acc.y += v0.y + v1.y + v2.y + v3.y;
            acc.z += v0.z + v1.z + v2.z + v3.z;
            acc.w += v0.w + v1.w + v2.w + v3.w;
        }
        for (; e < end; e++) {
            int s = col[e];
            float4 v = *(const float4*)&T[(size_t)s * 128 + lane * 4];
            acc.x += v.x; acc.y += v.y; acc.z += v.z; acc.w += v.w;
        }
        float sc = dinv[node];
        float4 u = make_float4(acc.x * sc + bb.x, acc.y * sc + bb.y,
                               acc.z * sc + bb.z, acc.w * sc + bb.w);
        *(float4*)&U[(size_t)node * 128 + lane * 4] = u;
        s4.x += u.x; s4.y += u.y; s4.z += u.z; s4.w += u.w;
        q4.x += u.x * u.x; q4.y += u.y * u.y; q4.z += u.z * u.z; q4.w += u.w * u.w;
    }

    // block-level stats reduce (8 warps -> smem), then one global atomic per feature
    __shared__ float ss[128], sq[128];
    int t = threadIdx.x;
    if (t < 128) { ss[t] = 0.f; sq[t] = 0.f; }
    __syncthreads();
    int f = lane * 4;
    atomicAdd(&ss[f + 0], s4.x); atomicAdd(&sq[f + 0], q4.x);
    atomicAdd(&ss[f + 1], s4.y); atomicAdd(&sq[f + 1], q4.y);
    atomicAdd(&ss[f + 2], s4.z); atomicAdd(&sq[f + 2], q4.z);
    atomicAdd(&ss[f + 3], s4.w); atomicAdd(&sq[f + 3], q4.w);
    __syncthreads();
    if (t < 128) {
        atomicAdd(&g_sum[t], ss[t]);
        atomicAdd(&g_sq [t], sq[t]);
    }
}

// ---------------- BN + ReLU (reads u directly) ----------------
__global__ void k_bnrelu(const float* __restrict__ U, const float* __restrict__ g,
                         const float* __restrict__ be, float* __restrict__ H, int nrows)
{
    int idx = blockIdx.x * blockDim.x + threadIdx.x;
    if (idx >= nrows * 128) return;
    int f = idx & 127;
    float u = U[idx];
    float h = (u - g_mean[f]) * g_istd[f] * g[f] + be[f];
    H[idx] = fmaxf(h, 0.f);
}

// ---------------- layer-3 GEMM (128 -> 16): T = dinv .* (A @ W3) ----------------
__global__ __launch_bounds__(256) void k_gemm16(const float* __restrict__ A,
                                                const float* __restrict__ W,
                                                const float* __restrict__ dinv,
                                                float* __restrict__ T, int nrows)
{
    __shared__ float Ws[128][16];
    for (int v = threadIdx.x; v < 128 * 16; v += blockDim.x)
        Ws[v >> 4][v & 15] = W[v];
    __syncthreads();

    int row = blockIdx.x * blockDim.x + threadIdx.x;
    if (row >= nrows) return;
    float acc[16];
    #pragma unroll
    for (int c = 0; c < 16; c++) acc[c] = 0.f;

    const float4* ar = (const float4*)&A[(size_t)row * 128];
    #pragma unroll 4
    for (int k4 = 0; k4 < 32; k4++) {
        float4 x = ar[k4];
        int k = k4 * 4;
        #pragma unroll
        for (int c = 0; c < 16; c++)
            acc[c] += x.x * Ws[k][c] + x.y * Ws[k + 1][c]
                    + x.z * Ws[k + 2][c] + x.w * Ws[k + 3][c];
    }
    float s = dinv[row];
    #pragma unroll
    for (int c = 0; c < 16; c += 4)
        *(float4*)&T[(size_t)row * 16 + c] =
            make_float4(acc[c] * s, acc[c + 1] * s, acc[c + 2] * s, acc[c + 3] * s);
}

// ---------------- CSR aggregation (OUTD=16): writes final output ----------------
// thread handles (node, 4-feature group): out = dinv*(self + sum_nbr) + b3
__global__ void k_agg16(const int* __restrict__ rowptr, const int* __restrict__ col,
                        const float* __restrict__ T, const float* __restrict__ dinv,
                        const float* __restrict__ b3, float* __restrict__ out, int n)
{
    int idx = blockIdx.x * blockDim.x + threadIdx.x;
    if (idx >= n * 4) return;
    int node = idx >> 2;
    int gp   = (idx & 3) * 4;
    float4 bb = *(const float4*)&b3[gp];

    int beg = rowptr[node], end = rowptr[node + 1];
    float4 acc = *(const float4*)&T[(size_t)node * 16 + gp];
    int e = beg;
    for (; e + 3 < end; e += 4) {
        int s0 = col[e], s1 = col[e + 1], s2 = col[e + 2], s3 = col[e + 3];
        float4 v0 = *(const float4*)&T[(size_t)s0 * 16 + gp];
        float4 v1 = *(const float4*)&T[(size_t)s1 * 16 + gp];
        float4 v2 = *(const float4*)&T[(size_t)s2 * 16 + gp];
        float4 v3 = *(const float4*)&T[(size_t)s3 * 16 + gp];
        acc.x += v0.x + v1.x + v2.x + v3.x;
        acc.y += v0.y + v1.y + v2.y + v3.y;
        acc.z += v0.z + v1.z + v2.z + v3.z;
        acc.w += v0.w + v1.w + v2.w + v3.w;
    }
    for (; e < end; e++) {
        int s = col[e];
        float4 v = *(const float4*)&T[(size_t)s * 16 + gp];
        acc.x += v.x; acc.y += v.y; acc.z += v.z; acc.w += v.w;
    }
    float sc = dinv[node];
    *(float4*)&out[(size_t)node * 16 + gp] =
        make_float4(acc.x * sc + bb.x, acc.y * sc + bb.y,
                    acc.z * sc + bb.z, acc.w * sc + bb.w);
}

// ---------------- launch ----------------
extern "C" void kernel_launch(void* const* d_in, const int* in_sizes, int n_in,
                              void* d_out, int out_size)
{
    const float* x   = (const float*)d_in[0];
    const int*   ei  = (const int*)d_in[1];   // int32 edge_index
    const float* W1  = (const float*)d_in[2];
    const float* b1  = (const float*)d_in[3];
    const float* g1  = (const float*)d_in[4];
    const float* be1 = (const float*)d_in[5];
    const float* W2  = (const float*)d_in[6];
    const float* b2  = (const float*)d_in[7];
    const float* g2  = (const float*)d_in[8];
    const float* be2 = (const float*)d_in[9];
    const float* W3  = (const float*)d_in[10];
    const float* b3  = (const float*)d_in[11];
    float*       out = (float*)d_out;

    int n = in_sizes[0] / IN_DIM;   // 50000
    int E = in_sizes[1] / 2;        // 800000

    int *cnt, *rowptr, *cursor, *col;
    float *dinv, *bufA, *bufB, *bufC;
    cudaGetSymbolAddress((void**)&cnt,    g_cnt);
    cudaGetSymbolAddress((void**)&rowptr, g_rowptr);
    cudaGetSymbolAddress((void**)&cursor, g_cursor);
    cudaGetSymbolAddress((void**)&col,    g_col);
    cudaGetSymbolAddress((void**)&dinv,   g_dinv);
    cudaGetSymbolAddress((void**)&bufA,   g_bufA);
    cudaGetSymbolAddress((void**)&bufB,   g_bufB);
    cudaGetSymbolAddress((void**)&bufC,   g_bufC);

    const int T256 = 256;
    int nb_n    = (n + T256 - 1) / T256;
    int nb_e    = (E + T256 - 1) / T256;
    int nb_rows = (n + 127) / 128;          // 391
    int nb_el   = (n * 128 + T256 - 1) / T256;
    int nb_a16  = (n * 4 + T256 - 1) / T256;
    const int AGG_BLOCKS = 444;             // 3552 warps, ~14 nodes/warp

    // CSR build (also computes dinv)
    k_zero_cnt<<<nb_n, T256>>>(cnt, n);
    k_hist    <<<nb_e, T256>>>(ei, cnt, E);
    k_scan    <<<1, 1024>>>(cnt, rowptr, cursor, dinv, n);
    k_fill    <<<nb_e, T256>>>(ei, cursor, col, E);

    // ---- layer 1 ----
    k_gemm_tc   <<<nb_rows, 256>>>(x, W1, dinv, bufA, n, IN_DIM);
    k_zero_stats<<<1, 128>>>();
    k_agg128    <<<AGG_BLOCKS, 256>>>(rowptr, col, bufA, dinv, b1, bufB, n);
    k_finalize_stats<<<1, 128>>>(n);
    k_bnrelu    <<<nb_el, T256>>>(bufB, g1, be1, bufC, n);

    // ---- layer 2 ----
    k_gemm_tc   <<<nb_rows, 256>>>(bufC, W2, dinv, bufA, n, HID);
    k_zero_stats<<<1, 128>>>();
    k_agg128    <<<AGG_BLOCKS, 256>>>(rowptr, col, bufA, dinv, b2, bufB, n);
    k_finalize_stats<<<1, 128>>>(n);
    k_bnrelu    <<<nb_el, T256>>>(bufB, g2, be2, bufC, n);

    // ---- layer 3 (128 -> 16, no BN) ----
    k_gemm16<<<nb_n, 256>>>(bufC, W3, dinv, bufA, n);
    k_agg16 <<<nb_a16, T256>>>(rowptr, col, bufA, dinv, b3, out, n);
}